// round 14
// baseline (speedup 1.0000x reference)
#include <cuda_runtime.h>
#include <cuda_bf16.h>
#include <cstdint>
#include <math.h>

#define CB     4
#define CH     56
#define CW     56
#define CDIM   512
#define CHEADS 16
#define CK     7
#define CD     32
#define CSP    (CH*CW)          // 3136
#define CM     (CB*CSP)         // 12544
#define WIN    14
#define NPOS   (WIN*WIN)        // 196

// ---- GEMM config (mma.sync bf16, 3-term split) ----
#define KA     1024             // A stored [Ahi | Alo]
#define KW     1536             // W stored [Whi | Wlo | Whi]
#define BK     32               // bf16 per k-iter
#define NIT    (KW/BK)          // 48
#define BM     128
#define BN     128
#define PITCH  80               // bytes per smem row (32 bf16 + 8 pad)
#define TILEB  (128*PITCH)      // 10240 per operand
#define STAGEB (2*TILEB)        // 20480
#define NSTAGE 4
#define SMEMB  (NSTAGE*STAGEB)  // 81920 (x2 CTAs = 160KB <= 228KB)

// Scratch
__device__ float g_q[CB*CHEADS*CSP*CD];
__device__ float g_k[CB*CHEADS*CSP*CD];
__device__ float g_v[CB*CHEADS*CSP*CD];
__device__ __nv_bfloat16 g_Ab[(size_t)CM * KA];        // 25.7 MB
__device__ __nv_bfloat16 g_Wb[(size_t)3 * CDIM * KW];  // 4.7 MB

// ---------------------------------------------------------------------------
__device__ __forceinline__ uint32_t smem_u32(const void* p) {
    uint32_t a;
    asm("{ .reg .u64 t; cvta.to.shared.u64 t, %1; cvt.u32.u64 %0, t; }"
        : "=r"(a) : "l"(p));
    return a;
}
__device__ __forceinline__ void cp16(uint32_t s, const void* g) {
    asm volatile("cp.async.cg.shared.global [%0], [%1], 16;" :: "r"(s), "l"(g));
}
__device__ __forceinline__ void cp_commit() {
    asm volatile("cp.async.commit_group;" ::: "memory");
}
__device__ __forceinline__ void cp_wait2() {
    asm volatile("cp.async.wait_group 2;" ::: "memory");
}
__device__ __forceinline__ void ldsm_x4(uint32_t* r, uint32_t a) {
    asm volatile("ldmatrix.sync.aligned.m8n8.x4.shared.b16 {%0,%1,%2,%3}, [%4];"
        : "=r"(r[0]), "=r"(r[1]), "=r"(r[2]), "=r"(r[3]) : "r"(a));
}
__device__ __forceinline__ void mma16816(float* d, const uint32_t* a, const uint32_t* b) {
    asm volatile("mma.sync.aligned.m16n8k16.row.col.f32.bf16.bf16.f32 "
        "{%0,%1,%2,%3}, {%4,%5,%6,%7}, {%8,%9}, {%0,%1,%2,%3};"
        : "+f"(d[0]), "+f"(d[1]), "+f"(d[2]), "+f"(d[3])
        : "r"(a[0]), "r"(a[1]), "r"(a[2]), "r"(a[3]), "r"(b[0]), "r"(b[1]));
}

// ---------------------------------------------------------------------------
// Prep: split fp32 A and W into bf16 hi/lo.
// ---------------------------------------------------------------------------
__global__ void __launch_bounds__(256) prep_kernel(
    const float* __restrict__ A,
    const float* __restrict__ Wq, const float* __restrict__ Wk, const float* __restrict__ Wv)
{
    const int idx = blockIdx.x * blockDim.x + threadIdx.x;
    const int totalA = CM * CDIM / 4;
    float4 v;
    if (idx < totalA) {
        v = ((const float4*)A)[idx];
        const int m = idx >> 7, c4 = idx & 127;
        __nv_bfloat162* b2 = (__nv_bfloat162*)(g_Ab + (size_t)m * KA + c4 * 4);
        __nv_bfloat16 h0 = __float2bfloat16(v.x), h1 = __float2bfloat16(v.y);
        __nv_bfloat16 h2 = __float2bfloat16(v.z), h3 = __float2bfloat16(v.w);
        __nv_bfloat162 hA, hB, lA, lB;
        hA.x = h0; hA.y = h1; hB.x = h2; hB.y = h3;
        lA.x = __float2bfloat16(v.x - __bfloat162float(h0));
        lA.y = __float2bfloat16(v.y - __bfloat162float(h1));
        lB.x = __float2bfloat16(v.z - __bfloat162float(h2));
        lB.y = __float2bfloat16(v.w - __bfloat162float(h3));
        b2[0] = hA; b2[1] = hB;          // hi at k
        b2[256] = lA; b2[257] = lB;      // lo at k+512
    } else {
        int t = idx - totalA;
        const int perW = CDIM * CDIM / 4;
        if (t >= 3 * perW) return;
        const int z = t / perW; t -= z * perW;
        const int n = t >> 7, c4 = t & 127;
        const float* W = (z == 0) ? Wq : (z == 1) ? Wk : Wv;
        v = ((const float4*)W)[(size_t)n * (CDIM / 4) + c4];
        __nv_bfloat162* b2 = (__nv_bfloat162*)(g_Wb + ((size_t)z * CDIM + n) * KW + c4 * 4);
        __nv_bfloat16 h0 = __float2bfloat16(v.x), h1 = __float2bfloat16(v.y);
        __nv_bfloat16 h2 = __float2bfloat16(v.z), h3 = __float2bfloat16(v.w);
        __nv_bfloat162 hA, hB, lA, lB;
        hA.x = h0; hA.y = h1; hB.x = h2; hB.y = h3;
        lA.x = __float2bfloat16(v.x - __bfloat162float(h0));
        lA.y = __float2bfloat16(v.y - __bfloat162float(h1));
        lB.x = __float2bfloat16(v.z - __bfloat162float(h2));
        lB.y = __float2bfloat16(v.w - __bfloat162float(h3));
        b2[0] = hA;   b2[1] = hB;        // seg0: hi
        b2[256] = lA; b2[257] = lB;      // seg1: lo
        b2[512] = hA; b2[513] = hB;      // seg2: hi
    }
}

__device__ __forceinline__ int a_kcol(int it) {
    return (it < 32) ? (it & 15) * BK : 512 + (it - 32) * BK;
}

// ---------------------------------------------------------------------------
// QKV GEMM via mma.sync bf16. 4-stage cp.async pipeline, prefetch-first.
// ---------------------------------------------------------------------------
__global__ void __launch_bounds__(256, 2) qkv_mma_kernel(
    const float* __restrict__ bq, const float* __restrict__ bk,
    const float* __restrict__ bv)
{
    extern __shared__ __align__(128) char smem[];
    const uint32_t sbase = smem_u32(smem);
    const int tid = threadIdx.x, wid = tid >> 5, lid = tid & 31;
    const int wm = wid & 1, wn = wid >> 1;

    const int m0 = blockIdx.x * BM;
    const int n0 = blockIdx.y * BN;
    const int z  = blockIdx.z;

    const char* Ag = (const char*)g_Ab + (size_t)m0 * KA * 2;
    const char* Bg = (const char*)g_Wb + ((size_t)z * CDIM + n0) * KW * 2;

    const int r_a0 = tid >> 1, c_a0 = (tid & 1) * 2;

    float acc[4][4][4];
    #pragma unroll
    for (int i = 0; i < 4; i++)
        #pragma unroll
        for (int j = 0; j < 4; j++)
            #pragma unroll
            for (int r = 0; r < 4; r++) acc[i][j][r] = 0.f;

    const uint32_t offA = (uint32_t)((wm * 64 + (lid & 15)) * PITCH + ((lid >> 4) << 4));
    const uint32_t offB = (uint32_t)((wn * 32 + ((lid >> 4) << 3) + (lid & 7)) * PITCH
                                     + (((lid >> 3) & 1) << 4));

    // ---- prologue: fill stages 0..2 ----
    #pragma unroll
    for (int s = 0; s < NSTAGE - 1; s++) {
        const uint32_t As = sbase + s * STAGEB;
        const uint32_t Bs = As + TILEB;
        const int ak = a_kcol(s), wk = s * BK;
        #pragma unroll
        for (int i = 0; i < 2; i++) {
            int c = c_a0 + i;
            cp16(As + r_a0 * PITCH + c * 16, Ag + ((size_t)r_a0 * KA + ak + c * 8) * 2);
            cp16(Bs + r_a0 * PITCH + c * 16, Bg + ((size_t)r_a0 * KW + wk + c * 8) * 2);
        }
        cp_commit();
    }

    // ---- mainloop: wait (<=2 pending) -> sync -> prefetch -> MMA ----
    for (int it = 0; it < NIT; it++) {
        cp_wait2();           // stage it complete
        __syncthreads();

        // prefetch it+3 into stage (it+3)%4 (= stage read by iter it-1)
        const int ld = it + NSTAGE - 1;
        if (ld < NIT) {
            const uint32_t As2 = sbase + (ld % NSTAGE) * STAGEB;
            const uint32_t Bs2 = As2 + TILEB;
            const int ak = a_kcol(ld), wk = ld * BK;
            #pragma unroll
            for (int i = 0; i < 2; i++) {
                int c = c_a0 + i;
                cp16(As2 + r_a0 * PITCH + c * 16, Ag + ((size_t)r_a0 * KA + ak + c * 8) * 2);
                cp16(Bs2 + r_a0 * PITCH + c * 16, Bg + ((size_t)r_a0 * KW + wk + c * 8) * 2);
            }
        }
        cp_commit();

        const int st = it % NSTAGE;
        const uint32_t As = sbase + st * STAGEB;
        const uint32_t Bs = As + TILEB;

        #pragma unroll
        for (int kk = 0; kk < 2; kk++) {
            uint32_t af[4][4];
            uint32_t bf[2][4];
            #pragma unroll
            for (int mf = 0; mf < 4; mf++)
                ldsm_x4(af[mf], As + offA + mf * (16 * PITCH) + kk * 32);
            #pragma unroll
            for (int np = 0; np < 2; np++)
                ldsm_x4(bf[np], Bs + offB + np * (16 * PITCH) + kk * 32);
            #pragma unroll
            for (int mf = 0; mf < 4; mf++)
                #pragma unroll
                for (int nf = 0; nf < 4; nf++)
                    mma16816(acc[mf][nf], af[mf], &bf[nf >> 1][(nf & 1) * 2]);
        }
    }

    // ---- epilogue: bias + scale + remap to [b, head, sp, d] ----
    const float* bias = (z == 0) ? bq : (z == 1) ? bk : bv;
    float* outp       = (z == 0) ? g_q : (z == 1) ? g_k : g_v;
    const float scale = (z == 0) ? 0.17677669529663688f : 1.0f;
    const int head = (n0 >> 5) + wn;
    const int ch0 = (lid & 3) * 2;

    #pragma unroll
    for (int nf = 0; nf < 4; nf++) {
        const int ch = nf * 8 + ch0;
        const float b0 = bias[n0 + wn * 32 + ch];
        const float b1 = bias[n0 + wn * 32 + ch + 1];
        #pragma unroll
        for (int mf = 0; mf < 4; mf++) {
            #pragma unroll
            for (int half = 0; half < 2; half++) {
                const int m = m0 + wm * 64 + mf * 16 + (lid >> 2) + half * 8;
                const int bb = m / CSP, sp = m - bb * CSP;
                float* dst = outp + (((size_t)bb * CHEADS + head) * CSP + sp) * CD + ch;
                float2 o;
                o.x = (acc[mf][nf][half * 2 + 0] + b0) * scale;
                o.y = (acc[mf][nf][half * 2 + 1] + b1) * scale;
                *(float2*)dst = o;
            }
        }
    }
}

// ---------------------------------------------------------------------------
// Neighborhood attention (unchanged R13 winner: fused single pass, split-d).
// ---------------------------------------------------------------------------
__global__ void __launch_bounds__(128, 4) natt_kernel(const float* __restrict__ rpb,
                                                      float* __restrict__ out)
{
    extern __shared__ float sm[];
    float* Ks   = sm;                  // NPOS*32
    float* Vs   = sm + NPOS*CD;        // NPOS*32
    float* rpbs = Vs + NPOS*CD;        // 13*13 = 169

    const int tile = blockIdx.x;       // 0..48 (7x7 tiles)
    const int ti = tile / 7, tj = tile - ti*7;
    const int h = blockIdx.y, b = blockIdx.z;
    const int i0 = ti*8, j0 = tj*8;
    const int r0 = min(max(i0 - 3, 0), CH - WIN);
    const int c0 = min(max(j0 - 3, 0), CW - WIN);
    const int tid = threadIdx.x;

    for (int idx = tid; idx < (2*CK-1)*(2*CK-1); idx += 128)
        rpbs[idx] = rpb[h*(2*CK-1)*(2*CK-1) + idx];

    const float* kb = g_k + (b*CHEADS + h) * CSP * CD;
    const float* vb = g_v + (b*CHEADS + h) * CSP * CD;

    for (int idx = tid; idx < WIN*WIN*8; idx += 128) {
        int row = idx / (WIN*8);
        int rem = idx - row*(WIN*8);
        int col = rem >> 3;
        int d4  = rem & 7;
        int goff = ((r0 + row)*CW + (c0 + col))*CD + d4*4;
        int p    = row*WIN + col;
        int soff = p*CD + ((d4 ^ (p & 7)) << 2);
        *(float4*)&Ks[soff] = *(const float4*)&kb[goff];
        *(float4*)&Vs[soff] = *(const float4*)&vb[goff];
    }
    __syncthreads();

    const int q     = tid >> 1;        // query 0..63
    const int dhalf = tid & 1;         // 0: chunks 0..3, 1: chunks 4..7
    const int cbase = dhalf * 4;
    const int qi = q >> 3, qj = q & 7;
    const int i = i0 + qi, j = j0 + qj;
    const int ni = min(max(i - 3, 0), CH - CK);
    const int nj = min(max(j - 3, 0), CW - CK);
    const int rl = ni - r0, cl = nj - c0;
    const int dbi = ni - i + (CK - 1), dbj = nj - j + (CK - 1);

    float4 q4[4];
    {
        const float* qp = g_q + ((b*CHEADS + h)*CSP + i*CW + j)*CD;
        #pragma unroll
        for (int cc = 0; cc < 4; cc++) q4[cc] = *(const float4*)&qp[(cbase + cc)*4];
    }

    float sum = 0.f;
    float4 c4[4];
    #pragma unroll
    for (int cc = 0; cc < 4; cc++) c4[cc] = make_float4(0.f, 0.f, 0.f, 0.f);

    #pragma unroll
    for (int ki = 0; ki < CK; ki++) {
        #pragma unroll
        for (int kj = 0; kj < CK; kj++) {
            const int p  = (rl + ki)*WIN + (cl + kj);
            const int sw = p & 7;
            const float* kp = Ks + p*CD;
            const float* vp = Vs + p*CD;
            float s = 0.f;
            #pragma unroll
            for (int cc = 0; cc < 4; cc++) {
                float4 kk = *(const float4*)&kp[((cbase + cc) ^ sw) << 2];
                s += q4[cc].x*kk.x + q4[cc].y*kk.y + q4[cc].z*kk.z + q4[cc].w*kk.w;
            }
            s += __shfl_xor_sync(0xFFFFFFFFu, s, 1);   // combine d-halves
            const float e = __expf(s + rpbs[(dbi + ki)*(2*CK-1) + (dbj + kj)]);
            sum += e;
            #pragma unroll
            for (int cc = 0; cc < 4; cc++) {
                float4 vv = *(const float4*)&vp[((cbase + cc) ^ sw) << 2];
                c4[cc].x += e*vv.x; c4[cc].y += e*vv.y;
                c4[cc].z += e*vv.z; c4[cc].w += e*vv.w;
            }
        }
    }

    const float inv = 1.f / sum;
    float* op = out + ((b*CH + i)*CW + j)*CDIM + h*CD;
    #pragma unroll
    for (int cc = 0; cc < 4; cc++) {
        *(float4*)&op[(cbase + cc)*4] = make_float4(c4[cc].x*inv, c4[cc].y*inv,
                                                    c4[cc].z*inv, c4[cc].w*inv);
    }
}

// ---------------------------------------------------------------------------
extern "C" void kernel_launch(void* const* d_in, const int* in_sizes, int n_in,
                              void* d_out, int out_size)
{
    const float* hidden = (const float*)d_in[0];
    const float* Wq = (const float*)d_in[1];
    const float* bq = (const float*)d_in[2];
    const float* Wk = (const float*)d_in[3];
    const float* bk = (const float*)d_in[4];
    const float* Wv = (const float*)d_in[5];
    const float* bv = (const float*)d_in[6];
    const float* rpb = (const float*)d_in[7];

    // 1) fp32 -> bf16 hi/lo packed operands
    const int totalP = CM*CDIM/4 + 3*CDIM*CDIM/4;
    prep_kernel<<<(totalP + 255) / 256, 256>>>(hidden, Wq, Wk, Wv);

    // 2) mma.sync QKV GEMM (4-stage pipeline, 2 CTAs/SM)
    cudaFuncSetAttribute(qkv_mma_kernel, cudaFuncAttributeMaxDynamicSharedMemorySize, SMEMB);
    qkv_mma_kernel<<<dim3(CM/BM, CDIM/BN, 3), 256, SMEMB>>>(bq, bk, bv);

    // 3) neighborhood attention (fused single pass, split-d)
    const int smem = (2*NPOS*CD + (2*CK-1)*(2*CK-1)) * (int)sizeof(float); // 50852 B
    cudaFuncSetAttribute(natt_kernel, cudaFuncAttributeMaxDynamicSharedMemorySize, smem);
    natt_kernel<<<dim3(49, CHEADS, CB), 128, smem>>>(rpb, (float*)d_out);
}

// round 15
// speedup vs baseline: 1.0404x; 1.0404x over previous
#include <cuda_runtime.h>
#include <cuda_bf16.h>
#include <cstdint>
#include <math.h>

#define CB     4
#define CH     56
#define CW     56
#define CDIM   512
#define CHEADS 16
#define CK     7
#define CD     32
#define CSP    (CH*CW)          // 3136
#define CM     (CB*CSP)         // 12544
#define WIN    14
#define NPOS   (WIN*WIN)        // 196

// ---- GEMM config (mma.sync bf16, 3-term split) ----
#define KA     1024             // A stored [Ahi | Alo]
#define KW     1536             // W stored [Whi | Wlo | Whi]
#define BK     32               // bf16 per k-iter
#define NIT    (KW/BK)          // 48
#define BM     128
#define BN     128
#define PITCH  80               // bytes per smem row (32 bf16 + 8 pad)
#define TILEB  (128*PITCH)      // 10240 per operand
#define STAGEB (2*TILEB)        // 20480
#define NSTAGE 3
#define SMEMB  (NSTAGE*STAGEB)  // 61440

// Scratch
__device__ float g_q[CB*CHEADS*CSP*CD];
__device__ float g_k[CB*CHEADS*CSP*CD];
__device__ float g_v[CB*CHEADS*CSP*CD];
__device__ __nv_bfloat16 g_Ab[(size_t)CM * KA];        // 25.7 MB
__device__ __nv_bfloat16 g_Wb[(size_t)3 * CDIM * KW];  // 4.7 MB

// ---------------------------------------------------------------------------
__device__ __forceinline__ uint32_t smem_u32(const void* p) {
    uint32_t a;
    asm("{ .reg .u64 t; cvta.to.shared.u64 t, %1; cvt.u32.u64 %0, t; }"
        : "=r"(a) : "l"(p));
    return a;
}
__device__ __forceinline__ void cp16(uint32_t s, const void* g) {
    asm volatile("cp.async.cg.shared.global [%0], [%1], 16;" :: "r"(s), "l"(g));
}
__device__ __forceinline__ void cp_commit() {
    asm volatile("cp.async.commit_group;" ::: "memory");
}
__device__ __forceinline__ void cp_wait1() {
    asm volatile("cp.async.wait_group 1;" ::: "memory");
}
__device__ __forceinline__ void ldsm_x4(uint32_t* r, uint32_t a) {
    asm volatile("ldmatrix.sync.aligned.m8n8.x4.shared.b16 {%0,%1,%2,%3}, [%4];"
        : "=r"(r[0]), "=r"(r[1]), "=r"(r[2]), "=r"(r[3]) : "r"(a));
}
__device__ __forceinline__ void mma16816(float* d, const uint32_t* a, const uint32_t* b) {
    asm volatile("mma.sync.aligned.m16n8k16.row.col.f32.bf16.bf16.f32 "
        "{%0,%1,%2,%3}, {%4,%5,%6,%7}, {%8,%9}, {%0,%1,%2,%3};"
        : "+f"(d[0]), "+f"(d[1]), "+f"(d[2]), "+f"(d[3])
        : "r"(a[0]), "r"(a[1]), "r"(a[2]), "r"(a[3]), "r"(b[0]), "r"(b[1]));
}

// ---------------------------------------------------------------------------
// Prep: split fp32 A and W into bf16 hi/lo.
// ---------------------------------------------------------------------------
__global__ void __launch_bounds__(256) prep_kernel(
    const float* __restrict__ A,
    const float* __restrict__ Wq, const float* __restrict__ Wk, const float* __restrict__ Wv)
{
    const int idx = blockIdx.x * blockDim.x + threadIdx.x;
    const int totalA = CM * CDIM / 4;
    float4 v;
    if (idx < totalA) {
        v = ((const float4*)A)[idx];
        const int m = idx >> 7, c4 = idx & 127;
        __nv_bfloat162* b2 = (__nv_bfloat162*)(g_Ab + (size_t)m * KA + c4 * 4);
        __nv_bfloat16 h0 = __float2bfloat16(v.x), h1 = __float2bfloat16(v.y);
        __nv_bfloat16 h2 = __float2bfloat16(v.z), h3 = __float2bfloat16(v.w);
        __nv_bfloat162 hA, hB, lA, lB;
        hA.x = h0; hA.y = h1; hB.x = h2; hB.y = h3;
        lA.x = __float2bfloat16(v.x - __bfloat162float(h0));
        lA.y = __float2bfloat16(v.y - __bfloat162float(h1));
        lB.x = __float2bfloat16(v.z - __bfloat162float(h2));
        lB.y = __float2bfloat16(v.w - __bfloat162float(h3));
        b2[0] = hA; b2[1] = hB;          // hi at k
        b2[256] = lA; b2[257] = lB;      // lo at k+512
    } else {
        int t = idx - totalA;
        const int perW = CDIM * CDIM / 4;
        if (t >= 3 * perW) return;
        const int z = t / perW; t -= z * perW;
        const int n = t >> 7, c4 = t & 127;
        const float* W = (z == 0) ? Wq : (z == 1) ? Wk : Wv;
        v = ((const float4*)W)[(size_t)n * (CDIM / 4) + c4];
        __nv_bfloat162* b2 = (__nv_bfloat162*)(g_Wb + ((size_t)z * CDIM + n) * KW + c4 * 4);
        __nv_bfloat16 h0 = __float2bfloat16(v.x), h1 = __float2bfloat16(v.y);
        __nv_bfloat16 h2 = __float2bfloat16(v.z), h3 = __float2bfloat16(v.w);
        __nv_bfloat162 hA, hB, lA, lB;
        hA.x = h0; hA.y = h1; hB.x = h2; hB.y = h3;
        lA.x = __float2bfloat16(v.x - __bfloat162float(h0));
        lA.y = __float2bfloat16(v.y - __bfloat162float(h1));
        lB.x = __float2bfloat16(v.z - __bfloat162float(h2));
        lB.y = __float2bfloat16(v.w - __bfloat162float(h3));
        b2[0] = hA;   b2[1] = hB;        // seg0: hi
        b2[256] = lA; b2[257] = lB;      // seg1: lo
        b2[512] = hA; b2[513] = hB;      // seg2: hi
    }
}

__device__ __forceinline__ int a_kcol(int it) {
    return (it < 32) ? (it & 15) * BK : 512 + (it - 32) * BK;
}

// ---------------------------------------------------------------------------
// QKV GEMM via mma.sync bf16 (exact R13 winning version: 3-stage, MMA-first).
// ---------------------------------------------------------------------------
__global__ void __launch_bounds__(256, 2) qkv_mma_kernel(
    const float* __restrict__ bq, const float* __restrict__ bk,
    const float* __restrict__ bv)
{
    extern __shared__ __align__(128) char smem[];
    const uint32_t sbase = smem_u32(smem);
    const int tid = threadIdx.x, wid = tid >> 5, lid = tid & 31;
    const int wm = wid & 1, wn = wid >> 1;

    const int m0 = blockIdx.x * BM;
    const int n0 = blockIdx.y * BN;
    const int z  = blockIdx.z;

    const char* Ag = (const char*)g_Ab + (size_t)m0 * KA * 2;
    const char* Bg = (const char*)g_Wb + ((size_t)z * CDIM + n0) * KW * 2;

    const int r_a0 = tid >> 1, c_a0 = (tid & 1) * 2;

    float acc[4][4][4];
    #pragma unroll
    for (int i = 0; i < 4; i++)
        #pragma unroll
        for (int j = 0; j < 4; j++)
            #pragma unroll
            for (int r = 0; r < 4; r++) acc[i][j][r] = 0.f;

    const uint32_t offA = (uint32_t)((wm * 64 + (lid & 15)) * PITCH + ((lid >> 4) << 4));
    const uint32_t offB = (uint32_t)((wn * 32 + ((lid >> 4) << 3) + (lid & 7)) * PITCH
                                     + (((lid >> 3) & 1) << 4));

    #pragma unroll
    for (int s = 0; s < NSTAGE - 1; s++) {
        const uint32_t As = sbase + s * STAGEB;
        const uint32_t Bs = As + TILEB;
        const int ak = a_kcol(s), wk = s * BK;
        #pragma unroll
        for (int i = 0; i < 2; i++) {
            int c = c_a0 + i;
            cp16(As + r_a0 * PITCH + c * 16, Ag + ((size_t)r_a0 * KA + ak + c * 8) * 2);
            cp16(Bs + r_a0 * PITCH + c * 16, Bg + ((size_t)r_a0 * KW + wk + c * 8) * 2);
        }
        cp_commit();
    }

    for (int it = 0; it < NIT; it++) {
        cp_wait1();
        __syncthreads();

        const int st = it % NSTAGE;
        const uint32_t As = sbase + st * STAGEB;
        const uint32_t Bs = As + TILEB;

        #pragma unroll
        for (int kk = 0; kk < 2; kk++) {
            uint32_t af[4][4];
            uint32_t bf[2][4];
            #pragma unroll
            for (int mf = 0; mf < 4; mf++)
                ldsm_x4(af[mf], As + offA + mf * (16 * PITCH) + kk * 32);
            #pragma unroll
            for (int np = 0; np < 2; np++)
                ldsm_x4(bf[np], Bs + offB + np * (16 * PITCH) + kk * 32);
            #pragma unroll
            for (int mf = 0; mf < 4; mf++)
                #pragma unroll
                for (int nf = 0; nf < 4; nf++)
                    mma16816(acc[mf][nf], af[mf], &bf[nf >> 1][(nf & 1) * 2]);
        }

        const int ld = it + NSTAGE - 1;
        if (ld < NIT) {
            const uint32_t As2 = sbase + (ld % NSTAGE) * STAGEB;
            const uint32_t Bs2 = As2 + TILEB;
            const int ak = a_kcol(ld), wk = ld * BK;
            #pragma unroll
            for (int i = 0; i < 2; i++) {
                int c = c_a0 + i;
                cp16(As2 + r_a0 * PITCH + c * 16, Ag + ((size_t)r_a0 * KA + ak + c * 8) * 2);
                cp16(Bs2 + r_a0 * PITCH + c * 16, Bg + ((size_t)r_a0 * KW + wk + c * 8) * 2);
            }
        }
        cp_commit();
    }

    const float* bias = (z == 0) ? bq : (z == 1) ? bk : bv;
    float* outp       = (z == 0) ? g_q : (z == 1) ? g_k : g_v;
    const float scale = (z == 0) ? 0.17677669529663688f : 1.0f;
    const int head = (n0 >> 5) + wn;
    const int ch0 = (lid & 3) * 2;

    #pragma unroll
    for (int nf = 0; nf < 4; nf++) {
        const int ch = nf * 8 + ch0;
        const float b0 = bias[n0 + wn * 32 + ch];
        const float b1 = bias[n0 + wn * 32 + ch + 1];
        #pragma unroll
        for (int mf = 0; mf < 4; mf++) {
            #pragma unroll
            for (int half = 0; half < 2; half++) {
                const int m = m0 + wm * 64 + mf * 16 + (lid >> 2) + half * 8;
                const int bb = m / CSP, sp = m - bb * CSP;
                float* dst = outp + (((size_t)bb * CHEADS + head) * CSP + sp) * CD + ch;
                float2 o;
                o.x = (acc[mf][nf][half * 2 + 0] + b0) * scale;
                o.y = (acc[mf][nf][half * 2 + 1] + b1) * scale;
                *(float2*)dst = o;
            }
        }
    }
}

// ---------------------------------------------------------------------------
// Neighborhood attention: fused single pass, split-d, TREE-REDUCED dot.
// Per-neighbor critical path cut from ~64cy (serial 16-FFMA chain) to ~24cy
// (4 independent 4-FFMA chains + pairwise combine).
// ---------------------------------------------------------------------------
__global__ void __launch_bounds__(128, 4) natt_kernel(const float* __restrict__ rpb,
                                                      float* __restrict__ out)
{
    extern __shared__ float sm[];
    float* Ks   = sm;                  // NPOS*32
    float* Vs   = sm + NPOS*CD;        // NPOS*32
    float* rpbs = Vs + NPOS*CD;        // 13*13 = 169

    const int tile = blockIdx.x;       // 0..48 (7x7 tiles)
    const int ti = tile / 7, tj = tile - ti*7;
    const int h = blockIdx.y, b = blockIdx.z;
    const int i0 = ti*8, j0 = tj*8;
    const int r0 = min(max(i0 - 3, 0), CH - WIN);
    const int c0 = min(max(j0 - 3, 0), CW - WIN);
    const int tid = threadIdx.x;

    for (int idx = tid; idx < (2*CK-1)*(2*CK-1); idx += 128)
        rpbs[idx] = rpb[h*(2*CK-1)*(2*CK-1) + idx];

    const float* kb = g_k + (b*CHEADS + h) * CSP * CD;
    const float* vb = g_v + (b*CHEADS + h) * CSP * CD;

    for (int idx = tid; idx < WIN*WIN*8; idx += 128) {
        int row = idx / (WIN*8);
        int rem = idx - row*(WIN*8);
        int col = rem >> 3;
        int d4  = rem & 7;
        int goff = ((r0 + row)*CW + (c0 + col))*CD + d4*4;
        int p    = row*WIN + col;
        int soff = p*CD + ((d4 ^ (p & 7)) << 2);
        *(float4*)&Ks[soff] = *(const float4*)&kb[goff];
        *(float4*)&Vs[soff] = *(const float4*)&vb[goff];
    }
    __syncthreads();

    const int q     = tid >> 1;        // query 0..63
    const int dhalf = tid & 1;         // 0: chunks 0..3, 1: chunks 4..7
    const int cbase = dhalf * 4;
    const int qi = q >> 3, qj = q & 7;
    const int i = i0 + qi, j = j0 + qj;
    const int ni = min(max(i - 3, 0), CH - CK);
    const int nj = min(max(j - 3, 0), CW - CK);
    const int rl = ni - r0, cl = nj - c0;
    const int dbi = ni - i + (CK - 1), dbj = nj - j + (CK - 1);

    float4 q4[4];
    {
        const float* qp = g_q + ((b*CHEADS + h)*CSP + i*CW + j)*CD;
        #pragma unroll
        for (int cc = 0; cc < 4; cc++) q4[cc] = *(const float4*)&qp[(cbase + cc)*4];
    }

    float sum0 = 0.f, sum1 = 0.f;
    float4 c4[4];
    #pragma unroll
    for (int cc = 0; cc < 4; cc++) c4[cc] = make_float4(0.f, 0.f, 0.f, 0.f);

    #pragma unroll
    for (int ki = 0; ki < CK; ki++) {
        #pragma unroll
        for (int kj = 0; kj < CK; kj++) {
            const int p  = (rl + ki)*WIN + (cl + kj);
            const int sw = p & 7;
            const float* kp = Ks + p*CD;
            const float* vp = Vs + p*CD;
            // tree-reduced dot: 4 independent per-chunk accumulators
            float ps[4];
            #pragma unroll
            for (int cc = 0; cc < 4; cc++) {
                float4 kk = *(const float4*)&kp[((cbase + cc) ^ sw) << 2];
                float t0 = q4[cc].x*kk.x;
                t0 = fmaf(q4[cc].y, kk.y, t0);
                t0 = fmaf(q4[cc].z, kk.z, t0);
                t0 = fmaf(q4[cc].w, kk.w, t0);
                ps[cc] = t0;
            }
            float s = (ps[0] + ps[1]) + (ps[2] + ps[3]);
            s += __shfl_xor_sync(0xFFFFFFFFu, s, 1);   // combine d-halves
            const float e = __expf(s + rpbs[(dbi + ki)*(2*CK-1) + (dbj + kj)]);
            if ((ki*CK + kj) & 1) sum1 += e; else sum0 += e;
            #pragma unroll
            for (int cc = 0; cc < 4; cc++) {
                float4 vv = *(const float4*)&vp[((cbase + cc) ^ sw) << 2];
                c4[cc].x += e*vv.x; c4[cc].y += e*vv.y;
                c4[cc].z += e*vv.z; c4[cc].w += e*vv.w;
            }
        }
    }

    const float inv = 1.f / (sum0 + sum1);
    float* op = out + ((b*CH + i)*CW + j)*CDIM + h*CD;
    #pragma unroll
    for (int cc = 0; cc < 4; cc++) {
        *(float4*)&op[(cbase + cc)*4] = make_float4(c4[cc].x*inv, c4[cc].y*inv,
                                                    c4[cc].z*inv, c4[cc].w*inv);
    }
}

// ---------------------------------------------------------------------------
extern "C" void kernel_launch(void* const* d_in, const int* in_sizes, int n_in,
                              void* d_out, int out_size)
{
    const float* hidden = (const float*)d_in[0];
    const float* Wq = (const float*)d_in[1];
    const float* bq = (const float*)d_in[2];
    const float* Wk = (const float*)d_in[3];
    const float* bk = (const float*)d_in[4];
    const float* Wv = (const float*)d_in[5];
    const float* bv = (const float*)d_in[6];
    const float* rpb = (const float*)d_in[7];

    // 1) fp32 -> bf16 hi/lo packed operands
    const int totalP = CM*CDIM/4 + 3*CDIM*CDIM/4;
    prep_kernel<<<(totalP + 255) / 256, 256>>>(hidden, Wq, Wk, Wv);

    // 2) mma.sync QKV GEMM (R13 winner: 3-stage, 2 CTAs/SM)
    cudaFuncSetAttribute(qkv_mma_kernel, cudaFuncAttributeMaxDynamicSharedMemorySize, SMEMB);
    qkv_mma_kernel<<<dim3(CM/BM, CDIM/BN, 3), 256, SMEMB>>>(bq, bk, bv);

    // 3) neighborhood attention (fused, split-d, tree-reduced dot)
    const int smem = (2*NPOS*CD + (2*CK-1)*(2*CK-1)) * (int)sizeof(float); // 50852 B
    cudaFuncSetAttribute(natt_kernel, cudaFuncAttributeMaxDynamicSharedMemorySize, smem);
    natt_kernel<<<dim3(49, CHEADS, CB), 128, smem>>>(rpb, (float*)d_out);
}

// round 16
// speedup vs baseline: 1.0447x; 1.0041x over previous
#include <cuda_runtime.h>
#include <cuda_bf16.h>
#include <cstdint>
#include <math.h>

#define CB     4
#define CH     56
#define CW     56
#define CDIM   512
#define CHEADS 16
#define CK     7
#define CD     32
#define CSP    (CH*CW)          // 3136
#define CM     (CB*CSP)         // 12544
#define WIN    14
#define NPOS   (WIN*WIN)        // 196
#define LOG2E  1.4426950408889634f

// ---- GEMM config (mma.sync bf16, 3-term split) ----
#define KA     1024             // A stored [Ahi | Alo]
#define KW     1536             // W stored [Whi | Wlo | Whi]
#define BK     32               // bf16 per k-iter
#define NIT    (KW/BK)          // 48
#define BM     128
#define BN     128
#define PITCH  80               // bytes per smem row (32 bf16 + 8 pad)
#define TILEB  (128*PITCH)      // 10240 per operand
#define STAGEB (2*TILEB)        // 20480
#define NSTAGE 3
#define SMEMB  (NSTAGE*STAGEB)  // 61440

// Scratch
__device__ float g_q[CB*CHEADS*CSP*CD];
__device__ float g_k[CB*CHEADS*CSP*CD];
__device__ float g_v[CB*CHEADS*CSP*CD];
__device__ __nv_bfloat16 g_Ab[(size_t)CM * KA];        // 25.7 MB
__device__ __nv_bfloat16 g_Wb[(size_t)3 * CDIM * KW];  // 4.7 MB

// ---------------------------------------------------------------------------
__device__ __forceinline__ uint32_t smem_u32(const void* p) {
    uint32_t a;
    asm("{ .reg .u64 t; cvta.to.shared.u64 t, %1; cvt.u32.u64 %0, t; }"
        : "=r"(a) : "l"(p));
    return a;
}
__device__ __forceinline__ void cp16(uint32_t s, const void* g) {
    asm volatile("cp.async.cg.shared.global [%0], [%1], 16;" :: "r"(s), "l"(g));
}
__device__ __forceinline__ void cp_commit() {
    asm volatile("cp.async.commit_group;" ::: "memory");
}
__device__ __forceinline__ void cp_wait1() {
    asm volatile("cp.async.wait_group 1;" ::: "memory");
}
__device__ __forceinline__ void ldsm_x4(uint32_t* r, uint32_t a) {
    asm volatile("ldmatrix.sync.aligned.m8n8.x4.shared.b16 {%0,%1,%2,%3}, [%4];"
        : "=r"(r[0]), "=r"(r[1]), "=r"(r[2]), "=r"(r[3]) : "r"(a));
}
__device__ __forceinline__ void mma16816(float* d, const uint32_t* a, const uint32_t* b) {
    asm volatile("mma.sync.aligned.m16n8k16.row.col.f32.bf16.bf16.f32 "
        "{%0,%1,%2,%3}, {%4,%5,%6,%7}, {%8,%9}, {%0,%1,%2,%3};"
        : "+f"(d[0]), "+f"(d[1]), "+f"(d[2]), "+f"(d[3])
        : "r"(a[0]), "r"(a[1]), "r"(a[2]), "r"(a[3]), "r"(b[0]), "r"(b[1]));
}

// ---------------------------------------------------------------------------
// Prep: split fp32 A and W into bf16 hi/lo.
// ---------------------------------------------------------------------------
__global__ void __launch_bounds__(256) prep_kernel(
    const float* __restrict__ A,
    const float* __restrict__ Wq, const float* __restrict__ Wk, const float* __restrict__ Wv)
{
    const int idx = blockIdx.x * blockDim.x + threadIdx.x;
    const int totalA = CM * CDIM / 4;
    float4 v;
    if (idx < totalA) {
        v = ((const float4*)A)[idx];
        const int m = idx >> 7, c4 = idx & 127;
        __nv_bfloat162* b2 = (__nv_bfloat162*)(g_Ab + (size_t)m * KA + c4 * 4);
        __nv_bfloat16 h0 = __float2bfloat16(v.x), h1 = __float2bfloat16(v.y);
        __nv_bfloat16 h2 = __float2bfloat16(v.z), h3 = __float2bfloat16(v.w);
        __nv_bfloat162 hA, hB, lA, lB;
        hA.x = h0; hA.y = h1; hB.x = h2; hB.y = h3;
        lA.x = __float2bfloat16(v.x - __bfloat162float(h0));
        lA.y = __float2bfloat16(v.y - __bfloat162float(h1));
        lB.x = __float2bfloat16(v.z - __bfloat162float(h2));
        lB.y = __float2bfloat16(v.w - __bfloat162float(h3));
        b2[0] = hA; b2[1] = hB;          // hi at k
        b2[256] = lA; b2[257] = lB;      // lo at k+512
    } else {
        int t = idx - totalA;
        const int perW = CDIM * CDIM / 4;
        if (t >= 3 * perW) return;
        const int z = t / perW; t -= z * perW;
        const int n = t >> 7, c4 = t & 127;
        const float* W = (z == 0) ? Wq : (z == 1) ? Wk : Wv;
        v = ((const float4*)W)[(size_t)n * (CDIM / 4) + c4];
        __nv_bfloat162* b2 = (__nv_bfloat162*)(g_Wb + ((size_t)z * CDIM + n) * KW + c4 * 4);
        __nv_bfloat16 h0 = __float2bfloat16(v.x), h1 = __float2bfloat16(v.y);
        __nv_bfloat16 h2 = __float2bfloat16(v.z), h3 = __float2bfloat16(v.w);
        __nv_bfloat162 hA, hB, lA, lB;
        hA.x = h0; hA.y = h1; hB.x = h2; hB.y = h3;
        lA.x = __float2bfloat16(v.x - __bfloat162float(h0));
        lA.y = __float2bfloat16(v.y - __bfloat162float(h1));
        lB.x = __float2bfloat16(v.z - __bfloat162float(h2));
        lB.y = __float2bfloat16(v.w - __bfloat162float(h3));
        b2[0] = hA;   b2[1] = hB;        // seg0: hi
        b2[256] = lA; b2[257] = lB;      // seg1: lo
        b2[512] = hA; b2[513] = hB;      // seg2: hi
    }
}

__device__ __forceinline__ int a_kcol(int it) {
    return (it < 32) ? (it & 15) * BK : 512 + (it - 32) * BK;
}

// ---------------------------------------------------------------------------
// QKV GEMM via mma.sync bf16 (exact R13/R15 winning version).
// ---------------------------------------------------------------------------
__global__ void __launch_bounds__(256, 2) qkv_mma_kernel(
    const float* __restrict__ bq, const float* __restrict__ bk,
    const float* __restrict__ bv)
{
    extern __shared__ __align__(128) char smem[];
    const uint32_t sbase = smem_u32(smem);
    const int tid = threadIdx.x, wid = tid >> 5, lid = tid & 31;
    const int wm = wid & 1, wn = wid >> 1;

    const int m0 = blockIdx.x * BM;
    const int n0 = blockIdx.y * BN;
    const int z  = blockIdx.z;

    const char* Ag = (const char*)g_Ab + (size_t)m0 * KA * 2;
    const char* Bg = (const char*)g_Wb + ((size_t)z * CDIM + n0) * KW * 2;

    const int r_a0 = tid >> 1, c_a0 = (tid & 1) * 2;

    float acc[4][4][4];
    #pragma unroll
    for (int i = 0; i < 4; i++)
        #pragma unroll
        for (int j = 0; j < 4; j++)
            #pragma unroll
            for (int r = 0; r < 4; r++) acc[i][j][r] = 0.f;

    const uint32_t offA = (uint32_t)((wm * 64 + (lid & 15)) * PITCH + ((lid >> 4) << 4));
    const uint32_t offB = (uint32_t)((wn * 32 + ((lid >> 4) << 3) + (lid & 7)) * PITCH
                                     + (((lid >> 3) & 1) << 4));

    #pragma unroll
    for (int s = 0; s < NSTAGE - 1; s++) {
        const uint32_t As = sbase + s * STAGEB;
        const uint32_t Bs = As + TILEB;
        const int ak = a_kcol(s), wk = s * BK;
        #pragma unroll
        for (int i = 0; i < 2; i++) {
            int c = c_a0 + i;
            cp16(As + r_a0 * PITCH + c * 16, Ag + ((size_t)r_a0 * KA + ak + c * 8) * 2);
            cp16(Bs + r_a0 * PITCH + c * 16, Bg + ((size_t)r_a0 * KW + wk + c * 8) * 2);
        }
        cp_commit();
    }

    for (int it = 0; it < NIT; it++) {
        cp_wait1();
        __syncthreads();

        const int st = it % NSTAGE;
        const uint32_t As = sbase + st * STAGEB;
        const uint32_t Bs = As + TILEB;

        #pragma unroll
        for (int kk = 0; kk < 2; kk++) {
            uint32_t af[4][4];
            uint32_t bf[2][4];
            #pragma unroll
            for (int mf = 0; mf < 4; mf++)
                ldsm_x4(af[mf], As + offA + mf * (16 * PITCH) + kk * 32);
            #pragma unroll
            for (int np = 0; np < 2; np++)
                ldsm_x4(bf[np], Bs + offB + np * (16 * PITCH) + kk * 32);
            #pragma unroll
            for (int mf = 0; mf < 4; mf++)
                #pragma unroll
                for (int nf = 0; nf < 4; nf++)
                    mma16816(acc[mf][nf], af[mf], &bf[nf >> 1][(nf & 1) * 2]);
        }

        const int ld = it + NSTAGE - 1;
        if (ld < NIT) {
            const uint32_t As2 = sbase + (ld % NSTAGE) * STAGEB;
            const uint32_t Bs2 = As2 + TILEB;
            const int ak = a_kcol(ld), wk = ld * BK;
            #pragma unroll
            for (int i = 0; i < 2; i++) {
                int c = c_a0 + i;
                cp16(As2 + r_a0 * PITCH + c * 16, Ag + ((size_t)r_a0 * KA + ak + c * 8) * 2);
                cp16(Bs2 + r_a0 * PITCH + c * 16, Bg + ((size_t)r_a0 * KW + wk + c * 8) * 2);
            }
        }
        cp_commit();
    }

    const float* bias = (z == 0) ? bq : (z == 1) ? bk : bv;
    float* outp       = (z == 0) ? g_q : (z == 1) ? g_k : g_v;
    const float scale = (z == 0) ? 0.17677669529663688f : 1.0f;
    const int head = (n0 >> 5) + wn;
    const int ch0 = (lid & 3) * 2;

    #pragma unroll
    for (int nf = 0; nf < 4; nf++) {
        const int ch = nf * 8 + ch0;
        const float b0 = bias[n0 + wn * 32 + ch];
        const float b1 = bias[n0 + wn * 32 + ch + 1];
        #pragma unroll
        for (int mf = 0; mf < 4; mf++) {
            #pragma unroll
            for (int half = 0; half < 2; half++) {
                const int m = m0 + wm * 64 + mf * 16 + (lid >> 2) + half * 8;
                const int bb = m / CSP, sp = m - bb * CSP;
                float* dst = outp + (((size_t)bb * CHEADS + head) * CSP + sp) * CD + ch;
                float2 o;
                o.x = (acc[mf][nf][half * 2 + 0] + b0) * scale;
                o.y = (acc[mf][nf][half * 2 + 1] + b1) * scale;
                *(float2*)dst = o;
            }
        }
    }
}

// ---------------------------------------------------------------------------
// Neighborhood attention: fused, split-d, EXP DEDUPLICATED across the pair.
// Neighbors processed two at a time; each pair thread computes ONE exp2
// (q and rpb pre-scaled by log2e) and exchanges it via shfl_xor(1).
// ---------------------------------------------------------------------------
__global__ void __launch_bounds__(128, 4) natt_kernel(const float* __restrict__ rpb,
                                                      float* __restrict__ out)
{
    extern __shared__ float sm[];
    float* Ks   = sm;                  // NPOS*32
    float* Vs   = sm + NPOS*CD;        // NPOS*32
    float* rpbs = Vs + NPOS*CD;        // 13*13 = 169

    const int tile = blockIdx.x;       // 0..48 (7x7 tiles)
    const int ti = tile / 7, tj = tile - ti*7;
    const int h = blockIdx.y, b = blockIdx.z;
    const int i0 = ti*8, j0 = tj*8;
    const int r0 = min(max(i0 - 3, 0), CH - WIN);
    const int c0 = min(max(j0 - 3, 0), CW - WIN);
    const int tid = threadIdx.x;

    for (int idx = tid; idx < (2*CK-1)*(2*CK-1); idx += 128)
        rpbs[idx] = rpb[h*(2*CK-1)*(2*CK-1) + idx] * LOG2E;

    const float* kb = g_k + (b*CHEADS + h) * CSP * CD;
    const float* vb = g_v + (b*CHEADS + h) * CSP * CD;

    for (int idx = tid; idx < WIN*WIN*8; idx += 128) {
        int row = idx / (WIN*8);
        int rem = idx - row*(WIN*8);
        int col = rem >> 3;
        int d4  = rem & 7;
        int goff = ((r0 + row)*CW + (c0 + col))*CD + d4*4;
        int p    = row*WIN + col;
        int soff = p*CD + ((d4 ^ (p & 7)) << 2);
        *(float4*)&Ks[soff] = *(const float4*)&kb[goff];
        *(float4*)&Vs[soff] = *(const float4*)&vb[goff];
    }
    __syncthreads();

    const int q     = tid >> 1;        // query 0..63
    const int dhalf = tid & 1;         // 0: chunks 0..3, 1: chunks 4..7
    const int cbase = dhalf * 4;
    const int qi = q >> 3, qj = q & 7;
    const int i = i0 + qi, j = j0 + qj;
    const int ni = min(max(i - 3, 0), CH - CK);
    const int nj = min(max(j - 3, 0), CW - CK);
    const int rl = ni - r0, cl = nj - c0;
    const int dbi = ni - i + (CK - 1), dbj = nj - j + (CK - 1);

    float4 q4[4];
    {
        const float* qp = g_q + ((b*CHEADS + h)*CSP + i*CW + j)*CD;
        #pragma unroll
        for (int cc = 0; cc < 4; cc++) {
            float4 t = *(const float4*)&qp[(cbase + cc)*4];
            t.x *= LOG2E; t.y *= LOG2E; t.z *= LOG2E; t.w *= LOG2E;
            q4[cc] = t;
        }
    }

    float sum = 0.f;
    float4 c4[4];
    #pragma unroll
    for (int cc = 0; cc < 4; cc++) c4[cc] = make_float4(0.f, 0.f, 0.f, 0.f);

    // half-dot of q (log2-scaled) with K at window position p
    #define NATT_DOT(p_, out_) do {                                          \
        const int sw_ = (p_) & 7;                                            \
        const float* kp_ = Ks + (p_)*CD;                                     \
        float ps0_, ps1_, ps2_, ps3_;                                        \
        {                                                                    \
            float4 kk = *(const float4*)&kp_[((cbase + 0) ^ sw_) << 2];      \
            ps0_ = fmaf(q4[0].w, kk.w, fmaf(q4[0].z, kk.z,                   \
                   fmaf(q4[0].y, kk.y, q4[0].x*kk.x)));                      \
        }                                                                    \
        {                                                                    \
            float4 kk = *(const float4*)&kp_[((cbase + 1) ^ sw_) << 2];      \
            ps1_ = fmaf(q4[1].w, kk.w, fmaf(q4[1].z, kk.z,                   \
                   fmaf(q4[1].y, kk.y, q4[1].x*kk.x)));                      \
        }                                                                    \
        {                                                                    \
            float4 kk = *(const float4*)&kp_[((cbase + 2) ^ sw_) << 2];      \
            ps2_ = fmaf(q4[2].w, kk.w, fmaf(q4[2].z, kk.z,                   \
                   fmaf(q4[2].y, kk.y, q4[2].x*kk.x)));                      \
        }                                                                    \
        {                                                                    \
            float4 kk = *(const float4*)&kp_[((cbase + 3) ^ sw_) << 2];      \
            ps3_ = fmaf(q4[3].w, kk.w, fmaf(q4[3].z, kk.z,                   \
                   fmaf(q4[3].y, kk.y, q4[3].x*kk.x)));                      \
        }                                                                    \
        (out_) = (ps0_ + ps1_) + (ps2_ + ps3_);                              \
    } while (0)

    #define NATT_ACCUM(p_, e_) do {                                          \
        const int sw_ = (p_) & 7;                                            \
        const float* vp_ = Vs + (p_)*CD;                                     \
        _Pragma("unroll")                                                     \
        for (int cc = 0; cc < 4; cc++) {                                      \
            float4 vv = *(const float4*)&vp_[((cbase + cc) ^ sw_) << 2];      \
            c4[cc].x += (e_)*vv.x; c4[cc].y += (e_)*vv.y;                     \
            c4[cc].z += (e_)*vv.z; c4[cc].w += (e_)*vv.w;                     \
        }                                                                     \
    } while (0)

    #pragma unroll
    for (int t = 0; t < 48; t += 2) {
        const int kia = t / 7,       kja = t - kia*7;
        const int kib = (t+1) / 7,   kjb = (t+1) - kib*7;
        const int pa = (rl + kia)*WIN + (cl + kja);
        const int pb = (rl + kib)*WIN + (cl + kjb);
        const float rba = rpbs[(dbi + kia)*(2*CK-1) + (dbj + kja)];
        const float rbb = rpbs[(dbi + kib)*(2*CK-1) + (dbj + kjb)];

        float sa, sb;
        NATT_DOT(pa, sa);
        NATT_DOT(pb, sb);

        // butterfly: each pair thread finalizes ONE neighbor's score
        const float mine  = dhalf ? sb : sa;
        const float other = dhalf ? sa : sb;
        const float recv  = __shfl_xor_sync(0xFFFFFFFFu, other, 1);
        const float e_own = exp2f(mine + recv + (dhalf ? rbb : rba));
        const float e_oth = __shfl_xor_sync(0xFFFFFFFFu, e_own, 1);
        const float ea = dhalf ? e_oth : e_own;
        const float eb = dhalf ? e_own : e_oth;

        sum += ea + eb;
        NATT_ACCUM(pa, ea);
        NATT_ACCUM(pb, eb);
    }
    {   // tail neighbor t = 48 (ki=6, kj=6)
        const int p = (rl + 6)*WIN + (cl + 6);
        float s;
        NATT_DOT(p, s);
        s += __shfl_xor_sync(0xFFFFFFFFu, s, 1);
        const float e = exp2f(s + rpbs[(dbi + 6)*(2*CK-1) + (dbj + 6)]);
        sum += e;
        NATT_ACCUM(p, e);
    }

    const float inv = 1.f / sum;
    float* op = out + ((b*CH + i)*CW + j)*CDIM + h*CD;
    #pragma unroll
    for (int cc = 0; cc < 4; cc++) {
        *(float4*)&op[(cbase + cc)*4] = make_float4(c4[cc].x*inv, c4[cc].y*inv,
                                                    c4[cc].z*inv, c4[cc].w*inv);
    }
    #undef NATT_DOT
    #undef NATT_ACCUM
}

// ---------------------------------------------------------------------------
extern "C" void kernel_launch(void* const* d_in, const int* in_sizes, int n_in,
                              void* d_out, int out_size)
{
    const float* hidden = (const float*)d_in[0];
    const float* Wq = (const float*)d_in[1];
    const float* bq = (const float*)d_in[2];
    const float* Wk = (const float*)d_in[3];
    const float* bk = (const float*)d_in[4];
    const float* Wv = (const float*)d_in[5];
    const float* bv = (const float*)d_in[6];
    const float* rpb = (const float*)d_in[7];

    // 1) fp32 -> bf16 hi/lo packed operands
    const int totalP = CM*CDIM/4 + 3*CDIM*CDIM/4;
    prep_kernel<<<(totalP + 255) / 256, 256>>>(hidden, Wq, Wk, Wv);

    // 2) mma.sync QKV GEMM (R13 winner: 3-stage, 2 CTAs/SM)
    cudaFuncSetAttribute(qkv_mma_kernel, cudaFuncAttributeMaxDynamicSharedMemorySize, SMEMB);
    qkv_mma_kernel<<<dim3(CM/BM, CDIM/BN, 3), 256, SMEMB>>>(bq, bk, bv);

    // 3) neighborhood attention (fused, split-d, dedup'd exp2)
    const int smem = (2*NPOS*CD + (2*CK-1)*(2*CK-1)) * (int)sizeof(float); // 50852 B
    cudaFuncSetAttribute(natt_kernel, cudaFuncAttributeMaxDynamicSharedMemorySize, smem);
    natt_kernel<<<dim3(49, CHEADS, CB), 128, smem>>>(rpb, (float*)d_out);
}

// round 17
// speedup vs baseline: 1.2916x; 1.2363x over previous
#include <cuda_runtime.h>
#include <cuda_fp16.h>
#include <cstdint>
#include <math.h>

#define CB     4
#define CH     56
#define CW     56
#define CDIM   512
#define CHEADS 16
#define CK     7
#define CD     32
#define CSP    (CH*CW)          // 3136
#define CM     (CB*CSP)         // 12544
#define WIN    14
#define NPOS   (WIN*WIN)        // 196
#define LOG2E  1.4426950408889634f

// ---- GEMM config (mma.sync fp16, 2-term split: A=[Ahi|Alo], W=Whi once) ----
#define KA     1024             // A stored [Ahi(512) | Alo(512)]
#define KWS    512              // W stored once (fp16 rounding)
#define BK     32               // fp16 per k-iter
#define NIT    (KA/BK)          // 32
#define BM     128
#define BN     128
#define PITCH  80               // bytes per smem row (32 fp16 + 16 pad)
#define TILEB  (128*PITCH)      // 10240 per operand
#define STAGEB (2*TILEB)        // 20480
#define NSTAGE 3
#define SMEMB  (NSTAGE*STAGEB)  // 61440

// Scratch
__device__ float g_q[CB*CHEADS*CSP*CD];
__device__ float g_k[CB*CHEADS*CSP*CD];
__device__ float g_v[CB*CHEADS*CSP*CD];
__device__ __half g_Ab[(size_t)CM * KA];          // 25.7 MB
__device__ __half g_Wb[(size_t)3 * CDIM * KWS];   // 1.6 MB

// ---------------------------------------------------------------------------
__device__ __forceinline__ uint32_t smem_u32(const void* p) {
    uint32_t a;
    asm("{ .reg .u64 t; cvta.to.shared.u64 t, %1; cvt.u32.u64 %0, t; }"
        : "=r"(a) : "l"(p));
    return a;
}
__device__ __forceinline__ void cp16(uint32_t s, const void* g) {
    asm volatile("cp.async.cg.shared.global [%0], [%1], 16;" :: "r"(s), "l"(g));
}
__device__ __forceinline__ void cp_commit() {
    asm volatile("cp.async.commit_group;" ::: "memory");
}
__device__ __forceinline__ void cp_wait1() {
    asm volatile("cp.async.wait_group 1;" ::: "memory");
}
__device__ __forceinline__ void ldsm_x4(uint32_t* r, uint32_t a) {
    asm volatile("ldmatrix.sync.aligned.m8n8.x4.shared.b16 {%0,%1,%2,%3}, [%4];"
        : "=r"(r[0]), "=r"(r[1]), "=r"(r[2]), "=r"(r[3]) : "r"(a));
}
__device__ __forceinline__ void mma16816(float* d, const uint32_t* a, const uint32_t* b) {
    asm volatile("mma.sync.aligned.m16n8k16.row.col.f32.f16.f16.f32 "
        "{%0,%1,%2,%3}, {%4,%5,%6,%7}, {%8,%9}, {%0,%1,%2,%3};"
        : "+f"(d[0]), "+f"(d[1]), "+f"(d[2]), "+f"(d[3])
        : "r"(a[0]), "r"(a[1]), "r"(a[2]), "r"(a[3]), "r"(b[0]), "r"(b[1]));
}

// ---------------------------------------------------------------------------
// Prep: A -> fp16 hi at k, fp16 lo at k+512. W -> single fp16 rounding.
// ---------------------------------------------------------------------------
__global__ void __launch_bounds__(256) prep_kernel(
    const float* __restrict__ A,
    const float* __restrict__ Wq, const float* __restrict__ Wk, const float* __restrict__ Wv)
{
    const int idx = blockIdx.x * blockDim.x + threadIdx.x;
    const int totalA = CM * CDIM / 4;
    if (idx < totalA) {
        float4 v = ((const float4*)A)[idx];
        const int m = idx >> 7, c4 = idx & 127;
        __half2* b2 = (__half2*)(g_Ab + (size_t)m * KA + c4 * 4);
        __half h0 = __float2half(v.x), h1 = __float2half(v.y);
        __half h2 = __float2half(v.z), h3 = __float2half(v.w);
        __half2 hA, hB, lA, lB;
        hA.x = h0; hA.y = h1; hB.x = h2; hB.y = h3;
        lA.x = __float2half(v.x - __half2float(h0));
        lA.y = __float2half(v.y - __half2float(h1));
        lB.x = __float2half(v.z - __half2float(h2));
        lB.y = __float2half(v.w - __half2float(h3));
        b2[0] = hA;   b2[1] = hB;        // hi at k
        b2[256] = lA; b2[257] = lB;      // lo at k+512
    } else {
        int t = idx - totalA;
        const int perW = CDIM * CDIM / 4;
        if (t >= 3 * perW) return;
        const int z = t / perW; t -= z * perW;
        const int n = t >> 7, c4 = t & 127;
        const float* W = (z == 0) ? Wq : (z == 1) ? Wk : Wv;
        float4 v = ((const float4*)W)[(size_t)n * (CDIM / 4) + c4];
        __half2* b2 = (__half2*)(g_Wb + ((size_t)z * CDIM + n) * KWS + c4 * 4);
        __half2 hA, hB;
        hA.x = __float2half(v.x); hA.y = __float2half(v.y);
        hB.x = __float2half(v.z); hB.y = __float2half(v.w);
        b2[0] = hA; b2[1] = hB;
    }
}

// ---------------------------------------------------------------------------
// QKV GEMM via mma.sync fp16. CTA tile 128x128, effective K=1024
// (A = [Ahi|Alo], B wraps over the single 512-wide Whi).
// ---------------------------------------------------------------------------
__global__ void __launch_bounds__(256, 2) qkv_mma_kernel(
    const float* __restrict__ bq, const float* __restrict__ bk,
    const float* __restrict__ bv)
{
    extern __shared__ __align__(128) char smem[];
    const uint32_t sbase = smem_u32(smem);
    const int tid = threadIdx.x, wid = tid >> 5, lid = tid & 31;
    const int wm = wid & 1, wn = wid >> 1;

    const int m0 = blockIdx.x * BM;
    const int n0 = blockIdx.y * BN;
    const int z  = blockIdx.z;

    const char* Ag = (const char*)g_Ab + (size_t)m0 * KA * 2;
    const char* Bg = (const char*)g_Wb + ((size_t)z * CDIM + n0) * KWS * 2;

    const int r_a0 = tid >> 1, c_a0 = (tid & 1) * 2;

    float acc[4][4][4];
    #pragma unroll
    for (int i = 0; i < 4; i++)
        #pragma unroll
        for (int j = 0; j < 4; j++)
            #pragma unroll
            for (int r = 0; r < 4; r++) acc[i][j][r] = 0.f;

    const uint32_t offA = (uint32_t)((wm * 64 + (lid & 15)) * PITCH + ((lid >> 4) << 4));
    const uint32_t offB = (uint32_t)((wn * 32 + ((lid >> 4) << 3) + (lid & 7)) * PITCH
                                     + (((lid >> 3) & 1) << 4));

    #pragma unroll
    for (int s = 0; s < NSTAGE - 1; s++) {
        const uint32_t As = sbase + s * STAGEB;
        const uint32_t Bs = As + TILEB;
        const int ak = s * BK, wk = (s & 15) * BK;
        #pragma unroll
        for (int i = 0; i < 2; i++) {
            int c = c_a0 + i;
            cp16(As + r_a0 * PITCH + c * 16, Ag + ((size_t)r_a0 * KA + ak + c * 8) * 2);
            cp16(Bs + r_a0 * PITCH + c * 16, Bg + ((size_t)r_a0 * KWS + wk + c * 8) * 2);
        }
        cp_commit();
    }

    for (int it = 0; it < NIT; it++) {
        cp_wait1();
        __syncthreads();

        const int st = it % NSTAGE;
        const uint32_t As = sbase + st * STAGEB;
        const uint32_t Bs = As + TILEB;

        #pragma unroll
        for (int kk = 0; kk < 2; kk++) {
            uint32_t af[4][4];
            uint32_t bf[2][4];
            #pragma unroll
            for (int mf = 0; mf < 4; mf++)
                ldsm_x4(af[mf], As + offA + mf * (16 * PITCH) + kk * 32);
            #pragma unroll
            for (int np = 0; np < 2; np++)
                ldsm_x4(bf[np], Bs + offB + np * (16 * PITCH) + kk * 32);
            #pragma unroll
            for (int mf = 0; mf < 4; mf++)
                #pragma unroll
                for (int nf = 0; nf < 4; nf++)
                    mma16816(acc[mf][nf], af[mf], &bf[nf >> 1][(nf & 1) * 2]);
        }

        const int ld = it + NSTAGE - 1;
        if (ld < NIT) {
            const uint32_t As2 = sbase + (ld % NSTAGE) * STAGEB;
            const uint32_t Bs2 = As2 + TILEB;
            const int ak = ld * BK, wk = (ld & 15) * BK;
            #pragma unroll
            for (int i = 0; i < 2; i++) {
                int c = c_a0 + i;
                cp16(As2 + r_a0 * PITCH + c * 16, Ag + ((size_t)r_a0 * KA + ak + c * 8) * 2);
                cp16(Bs2 + r_a0 * PITCH + c * 16, Bg + ((size_t)r_a0 * KWS + wk + c * 8) * 2);
            }
        }
        cp_commit();
    }

    const float* bias = (z == 0) ? bq : (z == 1) ? bk : bv;
    float* outp       = (z == 0) ? g_q : (z == 1) ? g_k : g_v;
    const float scale = (z == 0) ? 0.17677669529663688f : 1.0f;
    const int head = (n0 >> 5) + wn;
    const int ch0 = (lid & 3) * 2;

    #pragma unroll
    for (int nf = 0; nf < 4; nf++) {
        const int ch = nf * 8 + ch0;
        const float b0 = bias[n0 + wn * 32 + ch];
        const float b1 = bias[n0 + wn * 32 + ch + 1];
        #pragma unroll
        for (int mf = 0; mf < 4; mf++) {
            #pragma unroll
            for (int half = 0; half < 2; half++) {
                const int m = m0 + wm * 64 + mf * 16 + (lid >> 2) + half * 8;
                const int bb = m / CSP, sp = m - bb * CSP;
                float* dst = outp + (((size_t)bb * CHEADS + head) * CSP + sp) * CD + ch;
                float2 o;
                o.x = (acc[mf][nf][half * 2 + 0] + b0) * scale;
                o.y = (acc[mf][nf][half * 2 + 1] + b1) * scale;
                *(float2*)dst = o;
            }
        }
    }
}

// ---------------------------------------------------------------------------
// Neighborhood attention (exact R16 winner: fused, split-d, dedup'd exp2).
// ---------------------------------------------------------------------------
__global__ void __launch_bounds__(128, 4) natt_kernel(const float* __restrict__ rpb,
                                                      float* __restrict__ out)
{
    extern __shared__ float sm[];
    float* Ks   = sm;                  // NPOS*32
    float* Vs   = sm + NPOS*CD;        // NPOS*32
    float* rpbs = Vs + NPOS*CD;        // 13*13 = 169

    const int tile = blockIdx.x;       // 0..48 (7x7 tiles)
    const int ti = tile / 7, tj = tile - ti*7;
    const int h = blockIdx.y, b = blockIdx.z;
    const int i0 = ti*8, j0 = tj*8;
    const int r0 = min(max(i0 - 3, 0), CH - WIN);
    const int c0 = min(max(j0 - 3, 0), CW - WIN);
    const int tid = threadIdx.x;

    for (int idx = tid; idx < (2*CK-1)*(2*CK-1); idx += 128)
        rpbs[idx] = rpb[h*(2*CK-1)*(2*CK-1) + idx] * LOG2E;

    const float* kb = g_k + (b*CHEADS + h) * CSP * CD;
    const float* vb = g_v + (b*CHEADS + h) * CSP * CD;

    for (int idx = tid; idx < WIN*WIN*8; idx += 128) {
        int row = idx / (WIN*8);
        int rem = idx - row*(WIN*8);
        int col = rem >> 3;
        int d4  = rem & 7;
        int goff = ((r0 + row)*CW + (c0 + col))*CD + d4*4;
        int p    = row*WIN + col;
        int soff = p*CD + ((d4 ^ (p & 7)) << 2);
        *(float4*)&Ks[soff] = *(const float4*)&kb[goff];
        *(float4*)&Vs[soff] = *(const float4*)&vb[goff];
    }
    __syncthreads();

    const int q     = tid >> 1;        // query 0..63
    const int dhalf = tid & 1;         // 0: chunks 0..3, 1: chunks 4..7
    const int cbase = dhalf * 4;
    const int qi = q >> 3, qj = q & 7;
    const int i = i0 + qi, j = j0 + qj;
    const int ni = min(max(i - 3, 0), CH - CK);
    const int nj = min(max(j - 3, 0), CW - CK);
    const int rl = ni - r0, cl = nj - c0;
    const int dbi = ni - i + (CK - 1), dbj = nj - j + (CK - 1);

    float4 q4[4];
    {
        const float* qp = g_q + ((b*CHEADS + h)*CSP + i*CW + j)*CD;
        #pragma unroll
        for (int cc = 0; cc < 4; cc++) {
            float4 t = *(const float4*)&qp[(cbase + cc)*4];
            t.x *= LOG2E; t.y *= LOG2E; t.z *= LOG2E; t.w *= LOG2E;
            q4[cc] = t;
        }
    }

    float sum = 0.f;
    float4 c4[4];
    #pragma unroll
    for (int cc = 0; cc < 4; cc++) c4[cc] = make_float4(0.f, 0.f, 0.f, 0.f);

    #define NATT_DOT(p_, out_) do {                                          \
        const int sw_ = (p_) & 7;                                            \
        const float* kp_ = Ks + (p_)*CD;                                     \
        float ps0_, ps1_, ps2_, ps3_;                                        \
        {                                                                    \
            float4 kk = *(const float4*)&kp_[((cbase + 0) ^ sw_) << 2];      \
            ps0_ = fmaf(q4[0].w, kk.w, fmaf(q4[0].z, kk.z,                   \
                   fmaf(q4[0].y, kk.y, q4[0].x*kk.x)));                      \
        }                                                                    \
        {                                                                    \
            float4 kk = *(const float4*)&kp_[((cbase + 1) ^ sw_) << 2];      \
            ps1_ = fmaf(q4[1].w, kk.w, fmaf(q4[1].z, kk.z,                   \
                   fmaf(q4[1].y, kk.y, q4[1].x*kk.x)));                      \
        }                                                                    \
        {                                                                    \
            float4 kk = *(const float4*)&kp_[((cbase + 2) ^ sw_) << 2];      \
            ps2_ = fmaf(q4[2].w, kk.w, fmaf(q4[2].z, kk.z,                   \
                   fmaf(q4[2].y, kk.y, q4[2].x*kk.x)));                      \
        }                                                                    \
        {                                                                    \
            float4 kk = *(const float4*)&kp_[((cbase + 3) ^ sw_) << 2];      \
            ps3_ = fmaf(q4[3].w, kk.w, fmaf(q4[3].z, kk.z,                   \
                   fmaf(q4[3].y, kk.y, q4[3].x*kk.x)));                      \
        }                                                                    \
        (out_) = (ps0_ + ps1_) + (ps2_ + ps3_);                              \
    } while (0)

    #define NATT_ACCUM(p_, e_) do {                                          \
        const int sw_ = (p_) & 7;                                            \
        const float* vp_ = Vs + (p_)*CD;                                     \
        _Pragma("unroll")                                                     \
        for (int cc = 0; cc < 4; cc++) {                                      \
            float4 vv = *(const float4*)&vp_[((cbase + cc) ^ sw_) << 2];      \
            c4[cc].x += (e_)*vv.x; c4[cc].y += (e_)*vv.y;                     \
            c4[cc].z += (e_)*vv.z; c4[cc].w += (e_)*vv.w;                     \
        }                                                                     \
    } while (0)

    #pragma unroll
    for (int t = 0; t < 48; t += 2) {
        const int kia = t / 7,       kja = t - kia*7;
        const int kib = (t+1) / 7,   kjb = (t+1) - kib*7;
        const int pa = (rl + kia)*WIN + (cl + kja);
        const int pb = (rl + kib)*WIN + (cl + kjb);
        const float rba = rpbs[(dbi + kia)*(2*CK-1) + (dbj + kja)];
        const float rbb = rpbs[(dbi + kib)*(2*CK-1) + (dbj + kjb)];

        float sa, sb;
        NATT_DOT(pa, sa);
        NATT_DOT(pb, sb);

        const float mine  = dhalf ? sb : sa;
        const float other = dhalf ? sa : sb;
        const float recv  = __shfl_xor_sync(0xFFFFFFFFu, other, 1);
        const float e_own = exp2f(mine + recv + (dhalf ? rbb : rba));
        const float e_oth = __shfl_xor_sync(0xFFFFFFFFu, e_own, 1);
        const float ea = dhalf ? e_oth : e_own;
        const float eb = dhalf ? e_own : e_oth;

        sum += ea + eb;
        NATT_ACCUM(pa, ea);
        NATT_ACCUM(pb, eb);
    }
    {   // tail neighbor t = 48 (ki=6, kj=6)
        const int p = (rl + 6)*WIN + (cl + 6);
        float s;
        NATT_DOT(p, s);
        s += __shfl_xor_sync(0xFFFFFFFFu, s, 1);
        const float e = exp2f(s + rpbs[(dbi + 6)*(2*CK-1) + (dbj + 6)]);
        sum += e;
        NATT_ACCUM(p, e);
    }

    const float inv = 1.f / sum;
    float* op = out + ((b*CH + i)*CW + j)*CDIM + h*CD;
    #pragma unroll
    for (int cc = 0; cc < 4; cc++) {
        *(float4*)&op[(cbase + cc)*4] = make_float4(c4[cc].x*inv, c4[cc].y*inv,
                                                    c4[cc].z*inv, c4[cc].w*inv);
    }
    #undef NATT_DOT
    #undef NATT_ACCUM
}

// ---------------------------------------------------------------------------
extern "C" void kernel_launch(void* const* d_in, const int* in_sizes, int n_in,
                              void* d_out, int out_size)
{
    const float* hidden = (const float*)d_in[0];
    const float* Wq = (const float*)d_in[1];
    const float* bq = (const float*)d_in[2];
    const float* Wk = (const float*)d_in[3];
    const float* bk = (const float*)d_in[4];
    const float* Wv = (const float*)d_in[5];
    const float* bv = (const float*)d_in[6];
    const float* rpb = (const float*)d_in[7];

    // 1) fp32 -> fp16 operands (A hi/lo split, W single rounding)
    const int totalP = CM*CDIM/4 + 3*CDIM*CDIM/4;
    prep_kernel<<<(totalP + 255) / 256, 256>>>(hidden, Wq, Wk, Wv);

    // 2) mma.sync fp16 QKV GEMM (effective K=1024, 2 CTAs/SM)
    cudaFuncSetAttribute(qkv_mma_kernel, cudaFuncAttributeMaxDynamicSharedMemorySize, SMEMB);
    qkv_mma_kernel<<<dim3(CM/BM, CDIM/BN, 3), 256, SMEMB>>>(bq, bk, bv);

    // 3) neighborhood attention (R16 winner)
    const int smem = (2*NPOS*CD + (2*CK-1)*(2*CK-1)) * (int)sizeof(float); // 50852 B
    cudaFuncSetAttribute(natt_kernel, cudaFuncAttributeMaxDynamicSharedMemorySize, smem);
    natt_kernel<<<dim3(49, CHEADS, CB), 128, smem>>>(rpb, (float*)d_out);
}